// round 6
// baseline (speedup 1.0000x reference)
#include <cuda_runtime.h>

#define NN 262144              // total nodes
#define NE 2097152             // total edges
#define NG 1024                // graphs
#define NPG 256                // nodes per graph
#define MAXDEG 64              // per-node in-edge capacity (avg deg 8)

typedef unsigned long long u64;

// ---------------- scratch (static device memory) ----------------------------
__device__ int            g_is64;
__device__ int            g_cur[NN];                      // in-degree / fill cursor
__device__ unsigned char  g_col[(size_t)NN * MAXDEG];     // 16MB: local src ids

// ---------------- packed f32x2 helpers (Blackwell) --------------------------
#define FMA2(d, a, b, c) asm("fma.rn.f32x2 %0, %1, %2, %3;" : "=l"(d) : "l"(a), "l"(b), "l"(c))
#define ADD2(d, a, b)    asm("add.rn.f32x2 %0, %1, %2;"     : "=l"(d) : "l"(a), "l"(b))
#define PACK1(d, s)      asm("mov.b64 %0, {%1, %1};"        : "=l"(d) : "r"(s))
#define PACK2(d, lo, hi) asm("mov.b64 %0, {%1, %2};"        : "=l"(d) : "f"(lo), "f"(hi))
#define UNPK(lo, hi, v)  asm("mov.b64 {%0, %1}, %2;"        : "=f"(lo), "=f"(hi) : "l"(v))

// ---------------- dtype-agnostic index loads --------------------------------
__device__ __forceinline__ int edge_val(const void* ei, long long idx, int is64) {
    if (is64) return (int)((const long long*)ei)[idx];
    return ((const int*)ei)[idx];
}

// edge_index may be int32 or int64. If int64 (LE), every odd 32-bit word of
// the first 1024 values is 0 (node ids < 2^18); for int32 they are node ids.
__global__ void k_detect(const unsigned int* ei) {
    bool ok = true;
    for (int i = threadIdx.x; i < 1024; i += 32)
        if (ei[2 * i + 1] != 0u) ok = false;
    unsigned m = __ballot_sync(0xffffffffu, ok);
    if (threadIdx.x == 0) g_is64 = (m == 0xffffffffu) ? 1 : 0;
}

__global__ void k_zero() {
    int i = blockIdx.x * blockDim.x + threadIdx.x;
    if (i < NN) g_cur[i] = 0;
}

// single pass: build capped CSR; g_cur ends as the exact in-degree
__global__ void k_fill(const void* ei) {
    int e = blockIdx.x * blockDim.x + threadIdx.x;
    if (e < NE) {
        int is64 = g_is64;
        int s = edge_val(ei, e, is64);
        int d = edge_val(ei, (long long)NE + e, is64);
        int pos = atomicAdd(&g_cur[d], 1);
        if (pos < MAXDEG)
            g_col[(size_t)d * MAXDEG + pos] = (unsigned char)(s & 255);
    }
}

// ---------------- fully fused per-graph network ------------------------------
// block = one graph, 512 threads, 2 blocks/SM (32 warps).
// Aggregate-first: out_i = dinv_i*((sum_s dinv_s h_s + dinv_i h_i)@W) + b.
// SMEM (floats): U[8320] overlays {xd[256x12]@0, q1[256x12]@3072} then q2T[32x260]@0.
// h1d [256x34] pad-34 (conflict-free lane-channel gathers). No h2 matrix; no As.
#define SMEM_FUSED 85024

extern __shared__ float sm[];
__global__ void __launch_bounds__(512, 2) k_fused(
    const float* __restrict__ x,    const float* __restrict__ W1,
    const float* __restrict__ b1,   const float* __restrict__ W2,
    const float* __restrict__ b2,   const float* __restrict__ fc1W,
    const float* __restrict__ fc1b, const float* __restrict__ fc2W,
    const float* __restrict__ fc2b, const void*  __restrict__ sids,
    float* __restrict__ out)
{
    float* U     = sm;                 // 8320
    float* h1d   = U + 8320;           // 8704 (256 x 34)
    float* W2s   = h1d + 8704;         // 2048
    float* W1s   = W2s + 2048;         // 288
    float* b1s   = W1s + 288;          // 32
    float* b2s   = b1s + 32;           // 64
    float* f2    = b2s + 64;           // 64
    float* fc1bS = f2 + 64;            // 64
    float* ctx   = fc1bS + 64;         // 64
    float* ctxB  = ctx + 64;           // 64
    float* pool  = ctxB + 64;          // 256 (16 warps x 16)
    float* h2st  = pool + 256;         // 512 (8 stations x 64)
    float* dv    = h2st + 512;         // 256
    int*   knS   = (int*)(dv + 256);   // 256
    int*   stSl  = knS + 256;          // 256
    int*   sidS  = stSl + 256;         // 8

    float* xd  = U;                    // 256 x 12
    float* q1  = U + 3072;             // 256 x 12
    float* q2T = U;                    // 32 x 260 (transposed, pad 260)

    const int g = blockIdx.x, t = threadIdx.x;
    const int base = g * NPG;
    const int w = t >> 5, lane = t & 31;
    const int nid = t & 255, half = t >> 8;    // half warp-uniform (w<8 vs w>=8)

    // ---- phase A: degrees + weights + x*dinv --------------------------------
    int   cnt = g_cur[base + nid];
    float dvn = rsqrtf((float)cnt + 1.0f);
    if (half == 0) { knS[nid] = min(cnt, MAXDEG); dv[nid] = dvn; }
    {
        const float* xr = x + (size_t)(base + nid) * 9;
        if (half == 0) {
            #pragma unroll
            for (int c = 0; c < 5; c++) xd[nid * 12 + c] = xr[c] * dvn;
        } else {
            #pragma unroll
            for (int c = 5; c < 9; c++) xd[nid * 12 + c] = xr[c] * dvn;
        }
    }
    for (int i = t; i < 288; i += 512) W1s[i] = W1[i];
    {   const float4* s4 = (const float4*)W2;  float4* d4 = (float4*)W2s;
        if (t < 512) d4[t] = s4[t]; }
    if (t < 32) b1s[t] = b1[t];
    if (t < 64) { b2s[t] = b2[t]; f2[t] = fc2W[t]; fc1bS[t] = fc1b[t]; }
    if (t < 8)  sidS[t] = g_is64 ? (int)((const long long*)sids)[t]
                                 : ((const int*)sids)[t];
    __syncthreads();

    if (t < 256) {
        int sl = -1;
        #pragma unroll
        for (int s = 0; s < 8; s++) if (sidS[s] == t) sl = s;
        stSl[t] = sl;
    }

    const u64* cp = (const u64*)(g_col + (size_t)(base + nid) * MAXDEG);
    const int  kn = knS[nid];

    // ---- L1 aggregate (9-dim): q1[n] = sum_src xd[src] + xd[n] -------------
    if (half == 0) {        // channels 0..7
        float4 a03 = *(const float4*)&xd[nid * 12];
        float4 a47 = *(const float4*)&xd[nid * 12 + 4];
        for (int ch = 0; ch * 8 < kn; ch++) {
            u64 v = cp[ch];
            int lim = min(8, kn - ch * 8);
            for (int b = 0; b < lim; b++) {
                int j = (int)(v & 255u); v >>= 8;
                float4 s03 = *(const float4*)&xd[j * 12];
                float4 s47 = *(const float4*)&xd[j * 12 + 4];
                a03.x += s03.x; a03.y += s03.y; a03.z += s03.z; a03.w += s03.w;
                a47.x += s47.x; a47.y += s47.y; a47.z += s47.z; a47.w += s47.w;
            }
        }
        *(float4*)&q1[nid * 12]     = a03;
        *(float4*)&q1[nid * 12 + 4] = a47;
    } else {                // channel 8
        float a8 = xd[nid * 12 + 8];
        for (int ch = 0; ch * 8 < kn; ch++) {
            u64 v = cp[ch];
            int lim = min(8, kn - ch * 8);
            for (int b = 0; b < lim; b++) {
                int j = (int)(v & 255u); v >>= 8;
                a8 += xd[j * 12 + 8];
            }
        }
        q1[nid * 12 + 8] = a8;
    }
    __syncthreads();

    // ---- L1 linear 9->32, thread computes ch [16*half, +16) ----------------
    {
        float a[9];
        #pragma unroll
        for (int k = 0; k < 9; k++) a[k] = q1[nid * 12 + k];
        const int cb = half * 16;
        u64 acc[8];                      // acc[p] = channels (cb+2p, cb+2p+1)
        #pragma unroll
        for (int p = 0; p < 8; p++) acc[p] = 0ull;
        #pragma unroll
        for (int k = 0; k < 9; k++) {
            u64 ap; PACK1(ap, __float_as_uint(a[k]));
            const ulonglong2* wr = (const ulonglong2*)&W1s[k * 32 + cb];
            #pragma unroll
            for (int q = 0; q < 4; q++) {
                ulonglong2 wv = wr[q];
                FMA2(acc[2 * q],     ap, wv.x, acc[2 * q]);
                FMA2(acc[2 * q + 1], ap, wv.y, acc[2 * q + 1]);
            }
        }
        #pragma unroll
        for (int p = 0; p < 8; p++) {
            float lo, hi; UNPK(lo, hi, acc[p]);
            float2 o;
            o.x = fmaxf(fmaf(dvn, lo, b1s[cb + 2 * p]),     0.f) * dvn;
            o.y = fmaxf(fmaf(dvn, hi, b1s[cb + 2 * p + 1]), 0.f) * dvn;
            *(float2*)&h1d[nid * 34 + cb + 2 * p] = o;      // (34n+2p)*4 % 8 == 0
        }
    }
    __syncthreads();

    // ---- L2 aggregate: warp-per-node, lane = input channel (conflict-free) -
    // q2T[k][n] = sum_src h1d[src][k] + h1d[n][k]
    for (int nn = w; nn < 256; nn += 16) {
        int knn = knS[nn];
        const u64* cpn = (const u64*)(g_col + (size_t)(base + nn) * MAXDEG);
        float s = h1d[nn * 34 + lane];
        for (int ch = 0; ch * 8 < knn; ch++) {
            u64 v = cpn[ch];                       // warp-broadcast LDG
            int lim = min(8, knn - ch * 8);
            for (int b = 0; b < lim; b++) {
                int j = (int)(v & 255u); v >>= 8;
                s += h1d[j * 34 + lane];           // bank 2j+lane: 1 phase
            }
        }
        q2T[lane * 260 + nn] = s;                  // overlays dead xd/q1
    }
    __syncthreads();

    // ---- L2 linear 32->64: 2 nodes x 16 ch per thread, W2 warp-broadcast ---
    const int ng = t & 127, cg = t >> 7;           // cg warp-uniform
    u64 acc2[16];                                  // [i*8+p]: node 2ng+i, ch pair cg*16+2p
    #pragma unroll
    for (int p = 0; p < 16; p++) acc2[p] = 0ull;
    #pragma unroll
    for (int k = 0; k < 32; k++) {
        const ulonglong2* wr = (const ulonglong2*)&W2s[k * 64 + cg * 16];
        float2 av = *(const float2*)&q2T[k * 260 + 2 * ng];
        u64 a0; PACK1(a0, __float_as_uint(av.x));
        u64 a1; PACK1(a1, __float_as_uint(av.y));
        #pragma unroll
        for (int q = 0; q < 4; q++) {
            ulonglong2 wv = wr[q];
            FMA2(acc2[2 * q],         a0, wv.x, acc2[2 * q]);
            FMA2(acc2[2 * q + 1],     a0, wv.y, acc2[2 * q + 1]);
            FMA2(acc2[8 + 2 * q],     a1, wv.x, acc2[8 + 2 * q]);
            FMA2(acc2[8 + 2 * q + 1], a1, wv.y, acc2[8 + 2 * q + 1]);
        }
    }

    // ---- epilogue: ReLU+bias, station rows, pool partial in registers ------
    u64 psum[8];
    #pragma unroll
    for (int p = 0; p < 8; p++) psum[p] = 0ull;
    #pragma unroll
    for (int i = 0; i < 2; i++) {
        int node = 2 * ng + i;
        float dvi = dv[node];
        int sl = stSl[node];
        #pragma unroll
        for (int p = 0; p < 8; p++) {
            float lo, hi; UNPK(lo, hi, acc2[i * 8 + p]);
            float h0 = fmaxf(fmaf(dvi, lo, b2s[cg * 16 + 2 * p]),     0.f);
            float h1 = fmaxf(fmaf(dvi, hi, b2s[cg * 16 + 2 * p + 1]), 0.f);
            u64 hp; PACK2(hp, h0, h1);
            ADD2(psum[p], psum[p], hp);
            if (sl >= 0) {
                float2 o; o.x = h0; o.y = h1;
                *(float2*)&h2st[sl * 64 + cg * 16 + 2 * p] = o;
            }
        }
    }
    // warp shuffle-reduce pool partials (lanes span 32 ngs of this cg)
    #pragma unroll
    for (int off = 16; off; off >>= 1) {
        #pragma unroll
        for (int p = 0; p < 8; p++) {
            u64 o = __shfl_down_sync(0xffffffffu, psum[p], off);
            ADD2(psum[p], psum[p], o);
        }
    }
    if (lane == 0) {
        #pragma unroll
        for (int p = 0; p < 8; p++) {
            float lo, hi; UNPK(lo, hi, psum[p]);
            pool[w * 16 + 2 * p]     = lo;
            pool[w * 16 + 2 * p + 1] = hi;
        }
    }
    __syncthreads();

    // ---- ctx = mean pool (channel c: sum pool over the 4 warps of its cg) --
    if (t < 64) {
        int cgg = t >> 4, cc = t & 15;
        float s = 0.f;
        #pragma unroll
        for (int i = 0; i < 4; i++) s += pool[(4 * cgg + i) * 16 + cc];
        ctx[t] = s * (1.0f / 256.0f);
    }
    __syncthreads();

    // ---- ctxB = ctx @ fc1_W[64:128] + fc1_b ---------------------------------
    if (t < 64) {
        float s = fc1bS[t];
        #pragma unroll
        for (int k = 0; k < 64; k++) s += ctx[k] * __ldg(&fc1W[(64 + k) * 64 + t]);
        ctxB[t] = s;
    }
    __syncthreads();

    // ---- head: warp per station (fc1_W[0:64] via L2-hot LDG) ---------------
    if (w < 8) {
        float e0 = h2st[w * 64 + lane];
        float e1 = h2st[w * 64 + 32 + lane];
        float h0 = ctxB[lane], hb = ctxB[lane + 32];
        #pragma unroll
        for (int k = 0; k < 64; k++) {
            float ek = __shfl_sync(0xffffffffu, (k < 32) ? e0 : e1, k & 31);
            h0 += ek * __ldg(&fc1W[k * 64 + lane]);
            hb += ek * __ldg(&fc1W[k * 64 + lane + 32]);
        }
        h0 = fmaxf(h0, 0.f); hb = fmaxf(hb, 0.f);
        float q = h0 * f2[lane] + hb * f2[lane + 32];
        #pragma unroll
        for (int off = 16; off; off >>= 1)
            q += __shfl_down_sync(0xffffffffu, q, off);
        if (lane == 0) out[g * 8 + w] = q + fc2b[0];
    }
}

// ---------------------------------------------------------------------------
extern "C" void kernel_launch(void* const* d_in, const int* in_sizes, int n_in,
                              void* d_out, int out_size) {
    // Map inputs by element count. Unique sizes except the three 64-element
    // arrays, which appear in order (b2, fc1_b, fc2_W) under both insertion
    // and alphabetical conventions.
    const float *x = 0, *W1 = 0, *b1 = 0, *W2 = 0, *fc1W = 0, *fc2b = 0;
    const void  *ei = 0, *sids = 0;
    const float *sz64[3] = {0, 0, 0};
    int n64 = 0;
    for (int i = 0; i < n_in; i++) {
        switch (in_sizes[i]) {
            case 2359296: x    = (const float*)d_in[i]; break;
            case 4194304: ei   = d_in[i];               break;
            case 8:       sids = d_in[i];               break;
            case 288:     W1   = (const float*)d_in[i]; break;
            case 32:      b1   = (const float*)d_in[i]; break;
            case 2048:    W2   = (const float*)d_in[i]; break;
            case 8192:    fc1W = (const float*)d_in[i]; break;
            case 1:       fc2b = (const float*)d_in[i]; break;
            case 64:      if (n64 < 3) sz64[n64++] = (const float*)d_in[i]; break;
            default: break;
        }
    }
    const float* b2   = sz64[0];
    const float* fc1b = sz64[1];
    const float* fc2W = sz64[2];
    float* out = (float*)d_out;

    cudaFuncSetAttribute(k_fused, cudaFuncAttributeMaxDynamicSharedMemorySize, SMEM_FUSED);

    k_detect<<<1, 32>>>((const unsigned int*)ei);
    k_zero<<<NN / 256, 256>>>();
    k_fill<<<NE / 256, 256>>>(ei);
    k_fused<<<NG, 512, SMEM_FUSED>>>(x, W1, b1, W2, b2, fc1W, fc1b, fc2W, fc2b, sids, out);
}

// round 7
// speedup vs baseline: 1.0790x; 1.0790x over previous
#include <cuda_runtime.h>

#define NN 262144              // total nodes
#define NE 2097152             // total edges
#define NG 1024                // graphs
#define NPG 256                // nodes per graph
#define MAXDEG 64              // per-node in-edge capacity (avg deg 8)

typedef unsigned long long u64;

// ---------------- scratch (static device memory) ----------------------------
__device__ int            g_is64;
__device__ int            g_cur[NN];                      // in-degree / fill cursor
__device__ unsigned char  g_col[(size_t)NN * MAXDEG];     // 16MB: local src ids

// ---------------- packed f32x2 helpers (Blackwell) --------------------------
#define FMA2(d, a, b, c) asm("fma.rn.f32x2 %0, %1, %2, %3;" : "=l"(d) : "l"(a), "l"(b), "l"(c))
#define ADD2(d, a, b)    asm("add.rn.f32x2 %0, %1, %2;"     : "=l"(d) : "l"(a), "l"(b))
#define PACK1(d, s)      asm("mov.b64 %0, {%1, %1};"        : "=l"(d) : "r"(s))
#define PACK2(d, lo, hi) asm("mov.b64 %0, {%1, %2};"        : "=l"(d) : "f"(lo), "f"(hi))
#define UNPK(lo, hi, v)  asm("mov.b64 {%0, %1}, %2;"        : "=f"(lo), "=f"(hi) : "l"(v))

// ---------------- dtype-agnostic index loads --------------------------------
__device__ __forceinline__ int edge_val(const void* ei, long long idx, int is64) {
    if (is64) return (int)((const long long*)ei)[idx];
    return ((const int*)ei)[idx];
}

// k_zero also detects edge dtype: if int64 (LE), every odd 32-bit word of the
// first 1024 values is 0 (node ids < 2^18); for int32 they are node ids.
__global__ void k_zero(const unsigned int* ei) {
    int i = blockIdx.x * blockDim.x + threadIdx.x;
    if (i < NN) g_cur[i] = 0;
    if (blockIdx.x == 0 && threadIdx.x < 32) {
        bool ok = true;
        for (int k = threadIdx.x; k < 1024; k += 32)
            if (ei[2 * k + 1] != 0u) ok = false;
        unsigned m = __ballot_sync(0xffffffffu, ok);
        if (threadIdx.x == 0) g_is64 = (m == 0xffffffffu) ? 1 : 0;
    }
}

// single pass: build capped CSR; g_cur ends as the exact in-degree
__global__ void k_fill(const void* ei) {
    int e = blockIdx.x * blockDim.x + threadIdx.x;
    if (e < NE) {
        int is64 = g_is64;
        int s = edge_val(ei, e, is64);
        int d = edge_val(ei, (long long)NE + e, is64);
        int pos = atomicAdd(&g_cur[d], 1);
        if (pos < MAXDEG)
            g_col[(size_t)d * MAXDEG + pos] = (unsigned char)(s & 255);
    }
}

// ---------------- fully fused per-graph network ------------------------------
// block = one graph, 512 threads, 2 blocks/SM.
// Aggregate-first: out_i = dinv_i*((sum_s dinv_s h_s + dinv_i h_i)@W) + b.
// Edge lists padded to multiples of 8 with self-ids (correction folded into the
// accumulator init), stored transposed in SMEM -> branchless unrolled agg loops.
#define SMEM_FUSED 101408

extern __shared__ float sm[];
__global__ void __launch_bounds__(512, 2) k_fused(
    const float* __restrict__ x,    const float* __restrict__ W1,
    const float* __restrict__ b1,   const float* __restrict__ W2,
    const float* __restrict__ b2,   const float* __restrict__ fc1W,
    const float* __restrict__ fc1b, const float* __restrict__ fc2W,
    const float* __restrict__ fc2b, const void*  __restrict__ sids,
    float* __restrict__ out)
{
    float* U     = sm;                 // 8320: xd[256x12]@0, q1@3072; later q2T[32x260]@0
    float* h1d   = U + 8320;           // 8704 (256 x 34)
    float* W2s   = h1d + 8704;         // 2048
    float* W1s   = W2s + 2048;         // 288
    float* b1s   = W1s + 288;          // 32
    float* b2s   = b1s + 32;           // 64
    float* f2    = b2s + 64;           // 64
    float* fc1bS = f2 + 64;            // 64
    float* ctx   = fc1bS + 64;         // 64
    float* ctxB  = ctx + 64;           // 64
    float* pool  = ctxB + 64;          // 256 (16 warps x 16)
    float* h2st  = pool + 256;         // 512 (8 stations x 64)
    float* dv    = h2st + 512;         // 256
    int*   knS   = (int*)(dv + 256);   // 256
    int*   stSl  = knS + 256;          // 256
    int*   sidS  = stSl + 256;         // 8
    u64*   colS  = (u64*)(sidS + 8);   // 2048 u64 = 16KB, [ch][node] transposed

    float* xd  = U;                    // 256 x 12
    float* q1  = U + 3072;             // 256 x 12
    float* q2T = U;                    // 32 x 260

    const int g = blockIdx.x, t = threadIdx.x;
    const int base = g * NPG;
    const int w = t >> 5, lane = t & 31;
    const int nid = t & 255, half = t >> 8;    // half is warp-uniform

    // ---- phase A ------------------------------------------------------------
    int   cnt = g_cur[base + nid];
    int   kn  = min(cnt, MAXDEG);
    int   nch = (kn + 7) >> 3;
    float dvn = rsqrtf((float)cnt + 1.0f);
    if (half == 0) {
        knS[nid] = kn; dv[nid] = dvn;
        // pad edge words with self-id, store transposed to SMEM
        const u64* cp = (const u64*)(g_col + (size_t)(base + nid) * MAXDEG);
        u64 selfpat = 0x0101010101010101ull * (unsigned)nid;
        for (int ch = 0; ch < nch; ch++) {
            u64 v = cp[ch];
            int rem = kn - ch * 8;
            if (rem < 8) {
                u64 m = (1ull << (8 * rem)) - 1ull;
                v = (v & m) | (selfpat & ~m);
            }
            colS[ch * 256 + nid] = v;
        }
    } else {
        const float* xr = x + (size_t)(base + nid) * 9;
        #pragma unroll
        for (int c = 0; c < 9; c++) xd[nid * 12 + c] = xr[c] * dvn;
    }
    for (int i = t; i < 288; i += 512) W1s[i] = W1[i];
    {   const float4* s4 = (const float4*)W2;  float4* d4 = (float4*)W2s;
        if (t < 512) d4[t] = s4[t]; }
    if (t < 32) b1s[t] = b1[t];
    if (t < 64) { b2s[t] = b2[t]; f2[t] = fc2W[t]; fc1bS[t] = fc1b[t]; }
    if (t < 8)  sidS[t] = g_is64 ? (int)((const long long*)sids)[t]
                                 : ((const int*)sids)[t];
    __syncthreads();

    if (t < 256) {
        int sl = -1;
        #pragma unroll
        for (int s = 0; s < 8; s++) if (sidS[s] == t) sl = s;
        stSl[t] = sl;
    }

    const float padc = 1.0f - (float)(nch * 8 - kn);   // pad-self correction

    // ---- L1 aggregate (9-dim), branchless 8-unrolled chunks ----------------
    if (half == 0) {        // channels 0..7
        float a[8];
        #pragma unroll
        for (int c = 0; c < 8; c++) a[c] = padc * xd[nid * 12 + c];
        for (int ch = 0; ch < nch; ch++) {
            u64 v = colS[ch * 256 + nid];
            #pragma unroll
            for (int b = 0; b < 8; b++) {
                int j = (int)((v >> (8 * b)) & 255u);
                float4 s03 = *(const float4*)&xd[j * 12];
                float4 s47 = *(const float4*)&xd[j * 12 + 4];
                a[0] += s03.x; a[1] += s03.y; a[2] += s03.z; a[3] += s03.w;
                a[4] += s47.x; a[5] += s47.y; a[6] += s47.z; a[7] += s47.w;
            }
        }
        float4 o03; o03.x = a[0]; o03.y = a[1]; o03.z = a[2]; o03.w = a[3];
        float4 o47; o47.x = a[4]; o47.y = a[5]; o47.z = a[6]; o47.w = a[7];
        *(float4*)&q1[nid * 12]     = o03;
        *(float4*)&q1[nid * 12 + 4] = o47;
    } else {                // channel 8
        float a8 = padc * xd[nid * 12 + 8];
        for (int ch = 0; ch < nch; ch++) {
            u64 v = colS[ch * 256 + nid];
            float s0 = 0.f, s1 = 0.f;
            #pragma unroll
            for (int b = 0; b < 8; b += 2) {
                int j0 = (int)((v >> (8 * b)) & 255u);
                int j1 = (int)((v >> (8 * b + 8)) & 255u);
                s0 += xd[j0 * 12 + 8];
                s1 += xd[j1 * 12 + 8];
            }
            a8 += s0 + s1;
        }
        q1[nid * 12 + 8] = a8;
    }
    __syncthreads();

    // ---- L1 linear 9->32, thread computes ch [16*half, +16) ----------------
    {
        float a[9];
        #pragma unroll
        for (int k = 0; k < 9; k++) a[k] = q1[nid * 12 + k];
        const int cb = half * 16;
        u64 acc[8];                      // acc[p] = channels (cb+2p, cb+2p+1)
        #pragma unroll
        for (int p = 0; p < 8; p++) acc[p] = 0ull;
        #pragma unroll
        for (int k = 0; k < 9; k++) {
            u64 ap; PACK1(ap, __float_as_uint(a[k]));
            const ulonglong2* wr = (const ulonglong2*)&W1s[k * 32 + cb];
            #pragma unroll
            for (int q = 0; q < 4; q++) {
                ulonglong2 wv = wr[q];
                FMA2(acc[2 * q],     ap, wv.x, acc[2 * q]);
                FMA2(acc[2 * q + 1], ap, wv.y, acc[2 * q + 1]);
            }
        }
        #pragma unroll
        for (int p = 0; p < 8; p++) {
            float lo, hi; UNPK(lo, hi, acc[p]);
            float2 o;
            o.x = fmaxf(fmaf(dvn, lo, b1s[cb + 2 * p]),     0.f) * dvn;
            o.y = fmaxf(fmaf(dvn, hi, b1s[cb + 2 * p + 1]), 0.f) * dvn;
            *(float2*)&h1d[nid * 34 + cb + 2 * p] = o;
        }
    }
    __syncthreads();

    // ---- L2 aggregate: warp-per-node, lane = channel, 8-unrolled chunks ----
    for (int nn = w; nn < 256; nn += 16) {
        int knn  = knS[nn];
        int nchn = (knn + 7) >> 3;
        float pc = 1.0f - (float)(nchn * 8 - knn);
        float s  = pc * h1d[nn * 34 + lane];
        float s2 = 0.f;
        for (int ch = 0; ch < nchn; ch++) {
            u64 v = colS[ch * 256 + nn];           // broadcast LDS
            #pragma unroll
            for (int b = 0; b < 8; b += 2) {
                int j0 = (int)((v >> (8 * b)) & 255u);
                int j1 = (int)((v >> (8 * b + 8)) & 255u);
                s  += h1d[j0 * 34 + lane];          // bank 2j+lane: 1 phase
                s2 += h1d[j1 * 34 + lane];
            }
        }
        q2T[lane * 260 + nn] = s + s2;             // overlays dead xd/q1
    }
    __syncthreads();

    // ---- L2 linear 32->64: 2 nodes x 16 ch per thread, W2 warp-broadcast ---
    const int ng = t & 127, cg = t >> 7;           // cg warp-uniform
    u64 acc2[16];                                  // [i*8+p]: node 2ng+i, ch pair cg*16+2p
    #pragma unroll
    for (int p = 0; p < 16; p++) acc2[p] = 0ull;
    #pragma unroll
    for (int k = 0; k < 32; k++) {
        const ulonglong2* wr = (const ulonglong2*)&W2s[k * 64 + cg * 16];
        float2 av = *(const float2*)&q2T[k * 260 + 2 * ng];
        u64 a0; PACK1(a0, __float_as_uint(av.x));
        u64 a1; PACK1(a1, __float_as_uint(av.y));
        #pragma unroll
        for (int q = 0; q < 4; q++) {
            ulonglong2 wv = wr[q];
            FMA2(acc2[2 * q],         a0, wv.x, acc2[2 * q]);
            FMA2(acc2[2 * q + 1],     a0, wv.y, acc2[2 * q + 1]);
            FMA2(acc2[8 + 2 * q],     a1, wv.x, acc2[8 + 2 * q]);
            FMA2(acc2[8 + 2 * q + 1], a1, wv.y, acc2[8 + 2 * q + 1]);
        }
    }

    // ---- epilogue: ReLU+bias, station rows, pool partial in registers ------
    u64 psum[8];
    #pragma unroll
    for (int p = 0; p < 8; p++) psum[p] = 0ull;
    #pragma unroll
    for (int i = 0; i < 2; i++) {
        int node = 2 * ng + i;
        float dvi = dv[node];
        int sl = stSl[node];
        #pragma unroll
        for (int p = 0; p < 8; p++) {
            float lo, hi; UNPK(lo, hi, acc2[i * 8 + p]);
            float h0 = fmaxf(fmaf(dvi, lo, b2s[cg * 16 + 2 * p]),     0.f);
            float h1 = fmaxf(fmaf(dvi, hi, b2s[cg * 16 + 2 * p + 1]), 0.f);
            u64 hp; PACK2(hp, h0, h1);
            ADD2(psum[p], psum[p], hp);
            if (sl >= 0) {
                float2 o; o.x = h0; o.y = h1;
                *(float2*)&h2st[sl * 64 + cg * 16 + 2 * p] = o;
            }
        }
    }
    #pragma unroll
    for (int off = 16; off; off >>= 1) {
        #pragma unroll
        for (int p = 0; p < 8; p++) {
            u64 o = __shfl_down_sync(0xffffffffu, psum[p], off);
            ADD2(psum[p], psum[p], o);
        }
    }
    if (lane == 0) {
        #pragma unroll
        for (int p = 0; p < 8; p++) {
            float lo, hi; UNPK(lo, hi, psum[p]);
            pool[w * 16 + 2 * p]     = lo;
            pool[w * 16 + 2 * p + 1] = hi;
        }
    }
    __syncthreads();

    // ---- ctx = mean pool ----------------------------------------------------
    if (t < 64) {
        int cgg = t >> 4, cc = t & 15;
        float s = 0.f;
        #pragma unroll
        for (int i = 0; i < 4; i++) s += pool[(4 * cgg + i) * 16 + cc];
        ctx[t] = s * (1.0f / 256.0f);
    }
    __syncthreads();

    // ---- ctxB = ctx @ fc1_W[64:128] + fc1_b ---------------------------------
    if (t < 64) {
        float s = fc1bS[t];
        #pragma unroll
        for (int k = 0; k < 64; k++) s += ctx[k] * __ldg(&fc1W[(64 + k) * 64 + t]);
        ctxB[t] = s;
    }
    __syncthreads();

    // ---- head: warp per station (fc1_W[0:64] via L2-hot LDG) ---------------
    if (w < 8) {
        float e0 = h2st[w * 64 + lane];
        float e1 = h2st[w * 64 + 32 + lane];
        float h0 = ctxB[lane], hb = ctxB[lane + 32];
        #pragma unroll
        for (int k = 0; k < 64; k++) {
            float ek = __shfl_sync(0xffffffffu, (k < 32) ? e0 : e1, k & 31);
            h0 += ek * __ldg(&fc1W[k * 64 + lane]);
            hb += ek * __ldg(&fc1W[k * 64 + lane + 32]);
        }
        h0 = fmaxf(h0, 0.f); hb = fmaxf(hb, 0.f);
        float q = h0 * f2[lane] + hb * f2[lane + 32];
        #pragma unroll
        for (int off = 16; off; off >>= 1)
            q += __shfl_down_sync(0xffffffffu, q, off);
        if (lane == 0) out[g * 8 + w] = q + fc2b[0];
    }
}

// ---------------------------------------------------------------------------
extern "C" void kernel_launch(void* const* d_in, const int* in_sizes, int n_in,
                              void* d_out, int out_size) {
    // Map inputs by element count. Unique sizes except the three 64-element
    // arrays, which appear in order (b2, fc1_b, fc2_W) under both insertion
    // and alphabetical conventions.
    const float *x = 0, *W1 = 0, *b1 = 0, *W2 = 0, *fc1W = 0, *fc2b = 0;
    const void  *ei = 0, *sids = 0;
    const float *sz64[3] = {0, 0, 0};
    int n64 = 0;
    for (int i = 0; i < n_in; i++) {
        switch (in_sizes[i]) {
            case 2359296: x    = (const float*)d_in[i]; break;
            case 4194304: ei   = d_in[i];               break;
            case 8:       sids = d_in[i];               break;
            case 288:     W1   = (const float*)d_in[i]; break;
            case 32:      b1   = (const float*)d_in[i]; break;
            case 2048:    W2   = (const float*)d_in[i]; break;
            case 8192:    fc1W = (const float*)d_in[i]; break;
            case 1:       fc2b = (const float*)d_in[i]; break;
            case 64:      if (n64 < 3) sz64[n64++] = (const float*)d_in[i]; break;
            default: break;
        }
    }
    const float* b2   = sz64[0];
    const float* fc1b = sz64[1];
    const float* fc2W = sz64[2];
    float* out = (float*)d_out;

    cudaFuncSetAttribute(k_fused, cudaFuncAttributeMaxDynamicSharedMemorySize, SMEM_FUSED);

    k_zero<<<NN / 256, 256>>>((const unsigned int*)ei);
    k_fill<<<NE / 256, 256>>>(ei);
    k_fused<<<NG, 512, SMEM_FUSED>>>(x, W1, b1, W2, b2, fc1W, fc1b, fc2W, fc2b, sids, out);
}